// round 13
// baseline (speedup 1.0000x reference)
#include <cuda_runtime.h>
#include <cuda_fp16.h>

#define DIM 1024
#define NH 16
#define HD 64
#define BATCH 2
#define LQ 2048
#define LK 2048
// SCALE * log2(e): folded into the Q projection epilogue (fp32, pre-rounding)
#define QSCALE 0.18033688011112042f

// ---------------- scratch (allocation-free: __device__ globals) ----------------
__device__ __half g_qh[BATCH * LQ * DIM];
__device__ __half g_kh[BATCH * LK * DIM];
__device__ __half g_vh[BATCH * LK * DIM];
__device__ __half g_wq[DIM * DIM];
__device__ __half g_wk[DIM * DIM];
__device__ __half g_wv[DIM * DIM];
__device__ __half g_wo[DIM * DIM];
__device__ __half g_Qp[BATCH * LQ * DIM];
__device__ __half g_Kp[BATCH * LK * DIM];
__device__ __half g_Vp[BATCH * LK * DIM];
__device__ __half g_Ao[BATCH * LQ * DIM];

// ---------------- helpers ----------------
__device__ __forceinline__ float ex2(float x) {
    float y;
    asm("ex2.approx.ftz.f32 %0, %1;" : "=f"(y) : "f"(x));
    return y;
}
// two exps in one MUFU op; output IS the fp16 P pair
__device__ __forceinline__ unsigned h2ex2(float x0, float x1) {
    __half2 h = __floats2half2_rn(x0, x1);
    unsigned u = *(unsigned*)&h, r;
    asm("ex2.approx.f16x2 %0, %1;" : "=r"(r) : "r"(u));
    return r;
}
__device__ __forceinline__ void mma16(float* c, const unsigned* a, unsigned b0, unsigned b1) {
    asm volatile(
        "mma.sync.aligned.m16n8k16.row.col.f32.f16.f16.f32 "
        "{%0,%1,%2,%3}, {%4,%5,%6,%7}, {%8,%9}, {%0,%1,%2,%3};"
        : "+f"(c[0]), "+f"(c[1]), "+f"(c[2]), "+f"(c[3])
        : "r"(a[0]), "r"(a[1]), "r"(a[2]), "r"(a[3]), "r"(b0), "r"(b1));
}
__device__ __forceinline__ void ldsm4(unsigned& r0, unsigned& r1, unsigned& r2,
                                      unsigned& r3, unsigned addr) {
    asm volatile("ldmatrix.sync.aligned.m8n8.x4.shared.b16 {%0,%1,%2,%3}, [%4];"
                 : "=r"(r0), "=r"(r1), "=r"(r2), "=r"(r3) : "r"(addr));
}
__device__ __forceinline__ void ldsm4t(unsigned& r0, unsigned& r1, unsigned& r2,
                                       unsigned& r3, unsigned addr) {
    asm volatile("ldmatrix.sync.aligned.m8n8.x4.trans.shared.b16 {%0,%1,%2,%3}, [%4];"
                 : "=r"(r0), "=r"(r1), "=r"(r2), "=r"(r3) : "r"(addr));
}
__device__ __forceinline__ void cp16(unsigned s, const void* g) {
    asm volatile("cp.async.cg.shared.global [%0], [%1], 16;" :: "r"(s), "l"(g));
}
__device__ __forceinline__ void cp_commit() { asm volatile("cp.async.commit_group;"); }

// ---------------- convert kernels: f32 -> fp16 (RNE) ----------------
__global__ __launch_bounds__(256) void conv3(
    const float* __restrict__ a, const float* __restrict__ b, const float* __restrict__ c,
    __half* __restrict__ oa, __half* __restrict__ ob, __half* __restrict__ oc, int n4)
{
    const float* x = blockIdx.y == 0 ? a : blockIdx.y == 1 ? b : c;
    __half*      y = blockIdx.y == 0 ? oa : blockIdx.y == 1 ? ob : oc;
    int i = blockIdx.x * blockDim.x + threadIdx.x;
    if (i < n4) {
        float4 v = ((const float4*)x)[i];
        ((__half2*)y)[2 * i]     = __floats2half2_rn(v.x, v.y);
        ((__half2*)y)[2 * i + 1] = __floats2half2_rn(v.z, v.w);
    }
}
__global__ __launch_bounds__(256) void conv4(
    const float* __restrict__ a, const float* __restrict__ b,
    const float* __restrict__ c, const float* __restrict__ d,
    __half* __restrict__ oa, __half* __restrict__ ob,
    __half* __restrict__ oc, __half* __restrict__ od, int n4)
{
    const float* x = blockIdx.y == 0 ? a : blockIdx.y == 1 ? b : blockIdx.y == 2 ? c : d;
    __half*      y = blockIdx.y == 0 ? oa : blockIdx.y == 1 ? ob : blockIdx.y == 2 ? oc : od;
    int i = blockIdx.x * blockDim.x + threadIdx.x;
    if (i < n4) {
        float4 v = ((const float4*)x)[i];
        ((__half2*)y)[2 * i]     = __floats2half2_rn(v.x, v.y);
        ((__half2*)y)[2 * i + 1] = __floats2half2_rn(v.z, v.w);
    }
}

// ================= GEMM: C = (A @ W^T + bias) * osc, fp16 HMMA, 3-stage =================
#define GBM 128
#define GBN 128
#define GBK 64
#define HSR 72
#define GBUF (2 * GBM * HSR)
#define GEMM_SMEM (3 * GBUF * 2)

template <bool HALF_OUT>
__global__ __launch_bounds__(256) void gemm_h(
    const __half* __restrict__ A0, const __half* __restrict__ A1,
    const __half* __restrict__ A2,
    const __half* __restrict__ W0, const __half* __restrict__ W1,
    const __half* __restrict__ W2,
    const float* __restrict__ B0, const float* __restrict__ B1,
    const float* __restrict__ B2,
    void* __restrict__ C0, void* __restrict__ C1, void* __restrict__ C2,
    float s0_, float s1_, float s2_)
{
    extern __shared__ __half smh[];
    const unsigned sS = (unsigned)__cvta_generic_to_shared(smh);

    const int z = blockIdx.z;
    const __half* A  = z == 0 ? A0 : z == 1 ? A1 : A2;
    const __half* W  = z == 0 ? W0 : z == 1 ? W1 : W2;
    const float* bias = z == 0 ? B0 : z == 1 ? B1 : B2;
    void* Cv = z == 0 ? C0 : z == 1 ? C1 : C2;
    const float osc = z == 0 ? s0_ : z == 1 ? s1_ : s2_;

    const int t = threadIdx.x, lane = t & 31, wid = t >> 5;
    const int wm = (wid >> 2) * 64;
    const int wn = (wid & 3) * 32;
    const int c4 = lane & 3, g = lane >> 2, lrow = lane & 7;
    const int rA = ((lane >> 3) & 1) * 8 + lrow;  const int kA = (lane >> 4) * 8;
    const int rB = ((lane >> 4) & 1) * 8 + lrow;  const int kB = ((lane >> 3) & 1) * 8;
    const int bm = blockIdx.y * GBM, bn = blockIdx.x * GBN;

    const int srow = t >> 3;
    const int scol = (t & 7) * 8;

    float acc[4][4][4];
#pragma unroll
    for (int mt = 0; mt < 4; mt++)
#pragma unroll
        for (int nt = 0; nt < 4; nt++)
#pragma unroll
            for (int i = 0; i < 4; i++) acc[mt][nt][i] = 0.f;

    auto issue = [&](int kt, int b) {
        int k0 = kt * GBK;
        unsigned sbuf = sS + (unsigned)(b * GBUF) * 2;
#pragma unroll
        for (int r = 0; r < 4; r++) {
            int row = srow + r * 32;
            cp16(sbuf + (unsigned)(row * HSR + scol) * 2,
                 A + (size_t)(bm + row) * DIM + k0 + scol);
            cp16(sbuf + (unsigned)(GBM * HSR + row * HSR + scol) * 2,
                 W + (size_t)(bn + row) * DIM + k0 + scol);
        }
        cp_commit();
    };

    const int NT = DIM / GBK;   // 16
    issue(0, 0); issue(1, 1);

    for (int kt = 0; kt < NT; kt++) {
        const int b = kt % 3;
        if (kt < NT - 1) asm volatile("cp.async.wait_group 1;");
        else             asm volatile("cp.async.wait_group 0;");
        __syncthreads();
        if (kt + 2 < NT) issue(kt + 2, (kt + 2) % 3);

        const unsigned abase = sS + (unsigned)(b * GBUF + (wm + rA) * HSR + kA) * 2;
        const unsigned bbase = sS + (unsigned)(b * GBUF + GBM * HSR + (wn + rB) * HSR + kB) * 2;

#pragma unroll
        for (int ks = 0; ks < 4; ks++) {
            unsigned af[4][4], bf[2][4];
#pragma unroll
            for (int mt = 0; mt < 4; mt++)
                ldsm4(af[mt][0], af[mt][1], af[mt][2], af[mt][3],
                      abase + (unsigned)(mt * 16 * HSR) * 2 + ks * 32);
#pragma unroll
            for (int ntp = 0; ntp < 2; ntp++)
                ldsm4(bf[ntp][0], bf[ntp][1], bf[ntp][2], bf[ntp][3],
                      bbase + (unsigned)(ntp * 16 * HSR) * 2 + ks * 32);
#pragma unroll
            for (int mt = 0; mt < 4; mt++)
#pragma unroll
                for (int ntp = 0; ntp < 2; ntp++) {
                    mma16(acc[mt][2 * ntp],     af[mt], bf[ntp][0], bf[ntp][1]);
                    mma16(acc[mt][2 * ntp + 1], af[mt], bf[ntp][2], bf[ntp][3]);
                }
        }
        // no trailing sync: next iteration's head sync orders buffer reuse
    }

#pragma unroll
    for (int mt = 0; mt < 4; mt++) {
        int row = bm + wm + mt * 16 + g;
#pragma unroll
        for (int nt = 0; nt < 4; nt++) {
            int col = bn + wn + nt * 8 + 2 * c4;
            float b0 = __ldg(&bias[col]);
            float b1 = __ldg(&bias[col + 1]);
            float v00 = (acc[mt][nt][0] + b0) * osc, v01 = (acc[mt][nt][1] + b1) * osc;
            float v10 = (acc[mt][nt][2] + b0) * osc, v11 = (acc[mt][nt][3] + b1) * osc;
            if (HALF_OUT) {
                __half* C = (__half*)Cv;
                *(__half2*)&C[(size_t)row * DIM + col]       = __floats2half2_rn(v00, v01);
                *(__half2*)&C[(size_t)(row + 8) * DIM + col] = __floats2half2_rn(v10, v11);
            } else {
                float* C = (float*)Cv;
                *(float2*)&C[(size_t)row * DIM + col]       = make_float2(v00, v01);
                *(float2*)&C[(size_t)(row + 8) * DIM + col] = make_float2(v10, v11);
            }
        }
    }
}

// ================= flash attention: f16x2 exp, tensor-core row-sums =================
#define KV_TILE (64 * HSR)
#define PS_OFF  (4 * KV_TILE)
#define MSK_OFF ((4 * KV_TILE + 128 * HSR) * 2)
#define ATT_SMEM (MSK_OFF + 2 * 64 * 4)

__global__ __launch_bounds__(256) void attn_h(
    const __half* __restrict__ Qp, const __half* __restrict__ Kp,
    const __half* __restrict__ Vp, const int* __restrict__ kv_mask,
    __half* __restrict__ Ao)
{
    extern __shared__ __half smh[];
    __half* Ks = smh;
    __half* Vs = smh + 2 * KV_TILE;
    __half* Ps = smh + PS_OFF;
    int*   Msm = (int*)((char*)smh + MSK_OFF);

    const unsigned sK = (unsigned)__cvta_generic_to_shared(Ks);
    const unsigned sV = (unsigned)__cvta_generic_to_shared(Vs);
    const unsigned sP = (unsigned)__cvta_generic_to_shared(Ps);
    const unsigned sM = (unsigned)__cvta_generic_to_shared(Msm);

    const int t = threadIdx.x, lane = t & 31, w = t >> 5;
    const int c4 = lane & 3, g = lane >> 2, lrow = lane & 7;
    const int rA = lane & 15;                     const int kA = (lane >> 4) * 8;
    const int rB = ((lane >> 4) & 1) * 8 + lrow;  const int kB = ((lane >> 3) & 1) * 8;
    const int rV = ((lane >> 3) & 1) * 8 + lrow;  const int dV = (lane >> 4) * 8;
    const int qt = blockIdx.x, h = blockIdx.y, b = blockIdx.z;

    // ones-column B fragment (virtual V column of 1.0): zero memory traffic
    const unsigned onesb = (g == 0) ? 0x3C003C00u : 0u;

    const __half* Qb = Qp + ((size_t)(b * LQ + qt * 128)) * DIM + h * HD;
    const __half* Kb = Kp + (size_t)b * LK * DIM + h * HD;
    const __half* Vb = Vp + (size_t)b * LK * DIM + h * HD;
    const int*    mb = kv_mask + b * LK;

    auto issue_kv = [&](int kt, int buf) {
        const __half* Kg = Kb + (size_t)(kt * 64) * DIM;
        const __half* Vg = Vb + (size_t)(kt * 64) * DIM;
        int row0 = t >> 3, ch = (t & 7) * 8;
#pragma unroll
        for (int r = 0; r < 2; r++) {
            int row = row0 + r * 32;
            cp16(sK + (unsigned)(buf * KV_TILE + row * HSR + ch) * 2,
                 Kg + (size_t)row * DIM + ch);
            cp16(sV + (unsigned)(buf * KV_TILE + row * HSR + ch) * 2,
                 Vg + (size_t)row * DIM + ch);
        }
        if (t < 16) cp16(sM + buf * 256 + t * 16, mb + kt * 64 + t * 4);
        cp_commit();
    };

    issue_kv(0, 0);

    // stage Q (pre-scaled by SCALE*log2e in the projection) into Ps
    {
        int row0 = t >> 3, ch = (t & 7) * 8;
#pragma unroll
        for (int r = 0; r < 4; r++) {
            int row = row0 + r * 32;
            *(uint4*)&Ps[row * HSR + ch] = *(const uint4*)(Qb + (size_t)row * DIM + ch);
        }
    }
    __syncthreads();

    unsigned qf[4][4];
    {
        unsigned qbase = sP + (unsigned)((16 * w + rA) * HSR + kA) * 2;
#pragma unroll
        for (int ks = 0; ks < 4; ks++)
            ldsm4(qf[ks][0], qf[ks][1], qf[ks][2], qf[ks][3], qbase + ks * 32);
    }

    float O[8][4];
#pragma unroll
    for (int nt = 0; nt < 8; nt++)
#pragma unroll
        for (int i = 0; i < 4; i++) O[nt][i] = 0.f;
    float Ol[4] = {0.f, 0.f, 0.f, 0.f};   // l accumulator (ones-column C-frag)
    float mr0 = -1e30f, mr1 = -1e30f;

    for (int kt = 0; kt < LK / 64; kt++) {
        asm volatile("cp.async.wait_group 0;");
        __syncthreads();
        if (kt + 1 < LK / 64) issue_kv(kt + 1, (kt + 1) & 1);

        const int buf = kt & 1;
        const int* Mc = Msm + buf * 64;
        const unsigned kbase = sK + (unsigned)(buf * KV_TILE + rB * HSR + kB) * 2;
        const unsigned vbase = sV + (unsigned)(buf * KV_TILE + rV * HSR + dV) * 2;

        // S = Q K^T (log2-domain scores)
        float S[8][4];
#pragma unroll
        for (int nt = 0; nt < 8; nt++)
#pragma unroll
            for (int i = 0; i < 4; i++) S[nt][i] = 0.f;

#pragma unroll
        for (int ks = 0; ks < 4; ks++) {
#pragma unroll
            for (int ntp = 0; ntp < 4; ntp++) {
                unsigned b0, b1, b2, b3;
                ldsm4(b0, b1, b2, b3, kbase + (unsigned)(ntp * 16 * HSR) * 2 + ks * 32);
                mma16(S[2 * ntp],     qf[ks], b0, b1);
                mma16(S[2 * ntp + 1], qf[ks], b2, b3);
            }
        }

        // mask: -1e30 -> fp16 -inf -> ex2 -> 0
#pragma unroll
        for (int nt = 0; nt < 8; nt++) {
            if (!Mc[nt * 8 + 2 * c4])     { S[nt][0] = -1e30f; S[nt][2] = -1e30f; }
            if (!Mc[nt * 8 + 2 * c4 + 1]) { S[nt][1] = -1e30f; S[nt][3] = -1e30f; }
        }

        // running max
        float mx0 = -1e30f, mx1 = -1e30f;
#pragma unroll
        for (int nt = 0; nt < 8; nt++) {
            mx0 = fmaxf(mx0, fmaxf(S[nt][0], S[nt][1]));
            mx1 = fmaxf(mx1, fmaxf(S[nt][2], S[nt][3]));
        }
        mx0 = fmaxf(mx0, __shfl_xor_sync(0xffffffffu, mx0, 1));
        mx0 = fmaxf(mx0, __shfl_xor_sync(0xffffffffu, mx0, 2));
        mx1 = fmaxf(mx1, __shfl_xor_sync(0xffffffffu, mx1, 1));
        mx1 = fmaxf(mx1, __shfl_xor_sync(0xffffffffu, mx1, 2));

        float mn0 = fmaxf(mr0, mx0), mn1 = fmaxf(mr1, mx1);
        float a0 = ex2(mr0 - mn0), a1 = ex2(mr1 - mn1);
        mr0 = mn0; mr1 = mn1;

        // rescale O and l
#pragma unroll
        for (int nt = 0; nt < 8; nt++) {
            O[nt][0] *= a0; O[nt][1] *= a0; O[nt][2] *= a1; O[nt][3] *= a1;
        }
        Ol[0] *= a0; Ol[1] *= a0; Ol[2] *= a1; Ol[3] *= a1;

        // P = ex2(S - m) computed directly in fp16 pairs (these ARE the A-frags)
        unsigned P01[8], P23[8];
#pragma unroll
        for (int nt = 0; nt < 8; nt++) {
            P01[nt] = h2ex2(S[nt][0] - mn0, S[nt][1] - mn0);
            P23[nt] = h2ex2(S[nt][2] - mn1, S[nt][3] - mn1);
        }

        // O += P @ V; l += P @ ones (tensor-core row sums, no shfl)
#pragma unroll
        for (int kk = 0; kk < 4; kk++) {
            unsigned pa[4];
            pa[0] = P01[2 * kk];     pa[1] = P23[2 * kk];
            pa[2] = P01[2 * kk + 1]; pa[3] = P23[2 * kk + 1];
            mma16(Ol, pa, onesb, onesb);
#pragma unroll
            for (int ntp = 0; ntp < 4; ntp++) {
                unsigned v0, v1, v2, v3;
                ldsm4t(v0, v1, v2, v3,
                       vbase + (unsigned)(kk * 16 * HSR) * 2 + ntp * 32);
                mma16(O[2 * ntp],     pa, v0, v1);
                mma16(O[2 * ntp + 1], pa, v2, v3);
            }
        }
    }

    // l lives in column 0 (lane c4==0): broadcast within each quad
    float l0 = __shfl_sync(0xffffffffu, Ol[0], lane & 28);
    float l1 = __shfl_sync(0xffffffffu, Ol[2], lane & 28);
    float inv0 = 1.f / l0, inv1 = 1.f / l1;

    __half* Ob = Ao + ((size_t)(b * LQ + qt * 128)) * DIM + h * HD;
    int row0 = 16 * w + g;
#pragma unroll
    for (int nt = 0; nt < 8; nt++) {
        int col = nt * 8 + 2 * c4;
        *(__half2*)&Ob[(size_t)row0 * DIM + col] =
            __floats2half2_rn(O[nt][0] * inv0, O[nt][1] * inv0);
        *(__half2*)&Ob[(size_t)(row0 + 8) * DIM + col] =
            __floats2half2_rn(O[nt][2] * inv1, O[nt][3] * inv1);
    }
}

// ---------------- launch ----------------
extern "C" void kernel_launch(void* const* d_in, const int* in_sizes, int n_in,
                              void* d_out, int out_size)
{
    const float* q       = (const float*)d_in[0];
    const float* k       = (const float*)d_in[1];
    const float* v       = (const float*)d_in[2];
    const int*   kv_mask = (const int*)d_in[3];
    const float* Wq      = (const float*)d_in[4];
    const float* bq      = (const float*)d_in[5];
    const float* Wk      = (const float*)d_in[6];
    const float* bk      = (const float*)d_in[7];
    const float* Wv      = (const float*)d_in[8];
    const float* bv      = (const float*)d_in[9];
    const float* Wo      = (const float*)d_in[10];
    const float* bo      = (const float*)d_in[11];
    float* out = (float*)d_out;

    __half *qh, *kh, *vh, *wq, *wk, *wv, *wo, *Qp, *Kp, *Vp, *Ao;
    cudaGetSymbolAddress((void**)&qh, g_qh);
    cudaGetSymbolAddress((void**)&kh, g_kh);
    cudaGetSymbolAddress((void**)&vh, g_vh);
    cudaGetSymbolAddress((void**)&wq, g_wq);
    cudaGetSymbolAddress((void**)&wk, g_wk);
    cudaGetSymbolAddress((void**)&wv, g_wv);
    cudaGetSymbolAddress((void**)&wo, g_wo);
    cudaGetSymbolAddress((void**)&Qp, g_Qp);
    cudaGetSymbolAddress((void**)&Kp, g_Kp);
    cudaGetSymbolAddress((void**)&Vp, g_Vp);
    cudaGetSymbolAddress((void**)&Ao, g_Ao);

    cudaFuncSetAttribute(gemm_h<true>,  cudaFuncAttributeMaxDynamicSharedMemorySize, GEMM_SMEM);
    cudaFuncSetAttribute(gemm_h<false>, cudaFuncAttributeMaxDynamicSharedMemorySize, GEMM_SMEM);
    cudaFuncSetAttribute(attn_h, cudaFuncAttributeMaxDynamicSharedMemorySize, ATT_SMEM);

    const int ACT4 = BATCH * LQ * DIM / 4;
    const int W4   = DIM * DIM / 4;
    conv3<<<dim3(ACT4 / 256, 3), 256>>>(q, k, v, qh, kh, vh, ACT4);
    conv4<<<dim3(W4 / 256, 4), 256>>>(Wq, Wk, Wv, Wo, wq, wk, wv, wo, W4);

    gemm_h<true><<<dim3(DIM / GBN, (BATCH * LQ) / GBM, 3), 256, GEMM_SMEM>>>(
        qh, kh, vh, wq, wk, wv, bq, bk, bv, Qp, Kp, Vp,
        QSCALE, 1.0f, 1.0f);

    attn_h<<<dim3(LQ / 128, NH, BATCH), 256, ATT_SMEM>>>(Qp, Kp, Vp, kv_mask, Ao);

    gemm_h<false><<<dim3(DIM / GBN, (BATCH * LQ) / GBM, 1), 256, GEMM_SMEM>>>(
        Ao, Ao, Ao, wo, wo, wo, bo, bo, bo, out, out, out,
        1.0f, 1.0f, 1.0f);
}

// round 16
// speedup vs baseline: 1.0120x; 1.0120x over previous
#include <cuda_runtime.h>
#include <cuda_fp16.h>

#define DIM 1024
#define NH 16
#define HD 64
#define BATCH 2
#define LQ 2048
#define LK 2048
// SCALE * log2(e): folded into the Q projection epilogue (fp32, pre-rounding)
#define QSCALE 0.18033688011112042f

// ---------------- scratch (allocation-free: __device__ globals) ----------------
__device__ __half g_qh[BATCH * LQ * DIM];
__device__ __half g_kh[BATCH * LK * DIM];
__device__ __half g_vh[BATCH * LK * DIM];
__device__ __half g_wq[DIM * DIM];
__device__ __half g_wk[DIM * DIM];
__device__ __half g_wv[DIM * DIM];
__device__ __half g_wo[DIM * DIM];
__device__ __half g_Qp[BATCH * LQ * DIM];
__device__ __half g_Kp[BATCH * LK * DIM];
__device__ __half g_Vp[BATCH * LK * DIM];
__device__ __half g_Ao[BATCH * LQ * DIM];

// ---------------- helpers ----------------
__device__ __forceinline__ float ex2(float x) {
    float y;
    asm("ex2.approx.ftz.f32 %0, %1;" : "=f"(y) : "f"(x));
    return y;
}
// two exps in one MUFU op; output IS the fp16 P pair
__device__ __forceinline__ unsigned h2ex2(float x0, float x1) {
    __half2 h = __floats2half2_rn(x0, x1);
    unsigned u = *(unsigned*)&h, r;
    asm("ex2.approx.f16x2 %0, %1;" : "=r"(r) : "r"(u));
    return r;
}
__device__ __forceinline__ void mma16(float* c, const unsigned* a, unsigned b0, unsigned b1) {
    asm volatile(
        "mma.sync.aligned.m16n8k16.row.col.f32.f16.f16.f32 "
        "{%0,%1,%2,%3}, {%4,%5,%6,%7}, {%8,%9}, {%0,%1,%2,%3};"
        : "+f"(c[0]), "+f"(c[1]), "+f"(c[2]), "+f"(c[3])
        : "r"(a[0]), "r"(a[1]), "r"(a[2]), "r"(a[3]), "r"(b0), "r"(b1));
}
__device__ __forceinline__ void ldsm4(unsigned& r0, unsigned& r1, unsigned& r2,
                                      unsigned& r3, unsigned addr) {
    asm volatile("ldmatrix.sync.aligned.m8n8.x4.shared.b16 {%0,%1,%2,%3}, [%4];"
                 : "=r"(r0), "=r"(r1), "=r"(r2), "=r"(r3) : "r"(addr));
}
__device__ __forceinline__ void ldsm4t(unsigned& r0, unsigned& r1, unsigned& r2,
                                       unsigned& r3, unsigned addr) {
    asm volatile("ldmatrix.sync.aligned.m8n8.x4.trans.shared.b16 {%0,%1,%2,%3}, [%4];"
                 : "=r"(r0), "=r"(r1), "=r"(r2), "=r"(r3) : "r"(addr));
}
__device__ __forceinline__ void cp16(unsigned s, const void* g) {
    asm volatile("cp.async.cg.shared.global [%0], [%1], 16;" :: "r"(s), "l"(g));
}
__device__ __forceinline__ void cp_commit() { asm volatile("cp.async.commit_group;"); }

// ---------------- convert kernels: f32 -> fp16 (RNE) ----------------
__global__ __launch_bounds__(256) void conv3(
    const float* __restrict__ a, const float* __restrict__ b, const float* __restrict__ c,
    __half* __restrict__ oa, __half* __restrict__ ob, __half* __restrict__ oc, int n4)
{
    const float* x = blockIdx.y == 0 ? a : blockIdx.y == 1 ? b : c;
    __half*      y = blockIdx.y == 0 ? oa : blockIdx.y == 1 ? ob : oc;
    int i = blockIdx.x * blockDim.x + threadIdx.x;
    if (i < n4) {
        float4 v = ((const float4*)x)[i];
        ((__half2*)y)[2 * i]     = __floats2half2_rn(v.x, v.y);
        ((__half2*)y)[2 * i + 1] = __floats2half2_rn(v.z, v.w);
    }
}
__global__ __launch_bounds__(256) void conv4(
    const float* __restrict__ a, const float* __restrict__ b,
    const float* __restrict__ c, const float* __restrict__ d,
    __half* __restrict__ oa, __half* __restrict__ ob,
    __half* __restrict__ oc, __half* __restrict__ od, int n4)
{
    const float* x = blockIdx.y == 0 ? a : blockIdx.y == 1 ? b : blockIdx.y == 2 ? c : d;
    __half*      y = blockIdx.y == 0 ? oa : blockIdx.y == 1 ? ob : blockIdx.y == 2 ? oc : od;
    int i = blockIdx.x * blockDim.x + threadIdx.x;
    if (i < n4) {
        float4 v = ((const float4*)x)[i];
        ((__half2*)y)[2 * i]     = __floats2half2_rn(v.x, v.y);
        ((__half2*)y)[2 * i + 1] = __floats2half2_rn(v.z, v.w);
    }
}

// ================= GEMM: C = (A @ W^T + bias) * osc, fp16 HMMA, 3-stage =================
#define GBM 128
#define GBN 128
#define GBK 64
#define HSR 72
#define GBUF (2 * GBM * HSR)
#define GEMM_SMEM (3 * GBUF * 2)

template <bool HALF_OUT>
__global__ __launch_bounds__(256) void gemm_h(
    const __half* __restrict__ A0, const __half* __restrict__ A1,
    const __half* __restrict__ A2,
    const __half* __restrict__ W0, const __half* __restrict__ W1,
    const __half* __restrict__ W2,
    const float* __restrict__ B0, const float* __restrict__ B1,
    const float* __restrict__ B2,
    void* __restrict__ C0, void* __restrict__ C1, void* __restrict__ C2,
    float s0_, float s1_, float s2_)
{
    extern __shared__ __half smh[];
    const unsigned sS = (unsigned)__cvta_generic_to_shared(smh);

    const int z = blockIdx.z;
    const __half* A  = z == 0 ? A0 : z == 1 ? A1 : A2;
    const __half* W  = z == 0 ? W0 : z == 1 ? W1 : W2;
    const float* bias = z == 0 ? B0 : z == 1 ? B1 : B2;
    void* Cv = z == 0 ? C0 : z == 1 ? C1 : C2;
    const float osc = z == 0 ? s0_ : z == 1 ? s1_ : s2_;

    const int t = threadIdx.x, lane = t & 31, wid = t >> 5;
    const int wm = (wid >> 2) * 64;
    const int wn = (wid & 3) * 32;
    const int c4 = lane & 3, g = lane >> 2, lrow = lane & 7;
    const int rA = ((lane >> 3) & 1) * 8 + lrow;  const int kA = (lane >> 4) * 8;
    const int rB = ((lane >> 4) & 1) * 8 + lrow;  const int kB = ((lane >> 3) & 1) * 8;
    const int bm = blockIdx.y * GBM, bn = blockIdx.x * GBN;

    const int srow = t >> 3;
    const int scol = (t & 7) * 8;

    float acc[4][4][4];
#pragma unroll
    for (int mt = 0; mt < 4; mt++)
#pragma unroll
        for (int nt = 0; nt < 4; nt++)
#pragma unroll
            for (int i = 0; i < 4; i++) acc[mt][nt][i] = 0.f;

    auto issue = [&](int kt, int b) {
        int k0 = kt * GBK;
        unsigned sbuf = sS + (unsigned)(b * GBUF) * 2;
#pragma unroll
        for (int r = 0; r < 4; r++) {
            int row = srow + r * 32;
            cp16(sbuf + (unsigned)(row * HSR + scol) * 2,
                 A + (size_t)(bm + row) * DIM + k0 + scol);
            cp16(sbuf + (unsigned)(GBM * HSR + row * HSR + scol) * 2,
                 W + (size_t)(bn + row) * DIM + k0 + scol);
        }
        cp_commit();
    };

    const int NT = DIM / GBK;   // 16
    issue(0, 0); issue(1, 1);

    for (int kt = 0; kt < NT; kt++) {
        const int b = kt % 3;
        if (kt < NT - 1) asm volatile("cp.async.wait_group 1;");
        else             asm volatile("cp.async.wait_group 0;");
        __syncthreads();
        if (kt + 2 < NT) issue(kt + 2, (kt + 2) % 3);

        const unsigned abase = sS + (unsigned)(b * GBUF + (wm + rA) * HSR + kA) * 2;
        const unsigned bbase = sS + (unsigned)(b * GBUF + GBM * HSR + (wn + rB) * HSR + kB) * 2;

#pragma unroll
        for (int ks = 0; ks < 4; ks++) {
            unsigned af[4][4], bf[2][4];
#pragma unroll
            for (int mt = 0; mt < 4; mt++)
                ldsm4(af[mt][0], af[mt][1], af[mt][2], af[mt][3],
                      abase + (unsigned)(mt * 16 * HSR) * 2 + ks * 32);
#pragma unroll
            for (int ntp = 0; ntp < 2; ntp++)
                ldsm4(bf[ntp][0], bf[ntp][1], bf[ntp][2], bf[ntp][3],
                      bbase + (unsigned)(ntp * 16 * HSR) * 2 + ks * 32);
#pragma unroll
            for (int mt = 0; mt < 4; mt++)
#pragma unroll
                for (int ntp = 0; ntp < 2; ntp++) {
                    mma16(acc[mt][2 * ntp],     af[mt], bf[ntp][0], bf[ntp][1]);
                    mma16(acc[mt][2 * ntp + 1], af[mt], bf[ntp][2], bf[ntp][3]);
                }
        }
    }

#pragma unroll
    for (int mt = 0; mt < 4; mt++) {
        int row = bm + wm + mt * 16 + g;
#pragma unroll
        for (int nt = 0; nt < 4; nt++) {
            int col = bn + wn + nt * 8 + 2 * c4;
            float b0 = __ldg(&bias[col]);
            float b1 = __ldg(&bias[col + 1]);
            float v00 = (acc[mt][nt][0] + b0) * osc, v01 = (acc[mt][nt][1] + b1) * osc;
            float v10 = (acc[mt][nt][2] + b0) * osc, v11 = (acc[mt][nt][3] + b1) * osc;
            if (HALF_OUT) {
                __half* C = (__half*)Cv;
                *(__half2*)&C[(size_t)row * DIM + col]       = __floats2half2_rn(v00, v01);
                *(__half2*)&C[(size_t)(row + 8) * DIM + col] = __floats2half2_rn(v10, v11);
            } else {
                float* C = (float*)Cv;
                *(float2*)&C[(size_t)row * DIM + col]       = make_float2(v00, v01);
                *(float2*)&C[(size_t)(row + 8) * DIM + col] = make_float2(v10, v11);
            }
        }
    }
}

// ========== flash attention: PV pipelined one tile behind softmax ==========
// 4-stage KV ring. Iteration kt: S_kt MMAs issue, then PV_{kt-1} MMAs issue
// (tensor pipe stays busy), softmax(S_kt) runs under the PV drain, then O,l
// are rescaled AFTER the PV add (both at scale m_{kt-1} -- exact).
#define KV_TILE  (64 * HSR)
#define KV_STAGE (2 * KV_TILE)                    // K + V per stage, halves
#define PS_OFF   (4 * KV_STAGE)
#define MSK_OFF  ((PS_OFF + 128 * HSR) * 2)       // bytes
#define ATT_SMEM (MSK_OFF + 4 * 64 * 4)

__global__ __launch_bounds__(256, 2) void attn_h(
    const __half* __restrict__ Qp, const __half* __restrict__ Kp,
    const __half* __restrict__ Vp, const int* __restrict__ kv_mask,
    __half* __restrict__ Ao)
{
    extern __shared__ __half smh[];
    __half* Ps = smh + PS_OFF;
    int*   Msm = (int*)((char*)smh + MSK_OFF);

    const unsigned sKV = (unsigned)__cvta_generic_to_shared(smh);
    const unsigned sP  = (unsigned)__cvta_generic_to_shared(Ps);
    const unsigned sM  = (unsigned)__cvta_generic_to_shared(Msm);

    const int t = threadIdx.x, lane = t & 31, w = t >> 5;
    const int c4 = lane & 3, g = lane >> 2, lrow = lane & 7;
    const int rA = lane & 15;                     const int kA = (lane >> 4) * 8;
    const int rB = ((lane >> 4) & 1) * 8 + lrow;  const int kB = ((lane >> 3) & 1) * 8;
    const int rV = ((lane >> 3) & 1) * 8 + lrow;  const int dV = (lane >> 4) * 8;
    const int qt = blockIdx.x, h = blockIdx.y, b = blockIdx.z;

    // ones-column B fragment (virtual V column of 1.0)
    const unsigned onesb = (g == 0) ? 0x3C003C00u : 0u;

    const __half* Qb = Qp + ((size_t)(b * LQ + qt * 128)) * DIM + h * HD;
    const __half* Kb = Kp + (size_t)b * LK * DIM + h * HD;
    const __half* Vb = Vp + (size_t)b * LK * DIM + h * HD;
    const int*    mb = kv_mask + b * LK;

    auto issue_kv = [&](int kt, int s) {
        const __half* Kg = Kb + (size_t)(kt * 64) * DIM;
        const __half* Vg = Vb + (size_t)(kt * 64) * DIM;
        int row0 = t >> 3, ch = (t & 7) * 8;
        unsigned base = sKV + (unsigned)(s * KV_STAGE) * 2;
#pragma unroll
        for (int r = 0; r < 2; r++) {
            int row = row0 + r * 32;
            cp16(base + (unsigned)(row * HSR + ch) * 2,
                 Kg + (size_t)row * DIM + ch);
            cp16(base + (unsigned)(KV_TILE + row * HSR + ch) * 2,
                 Vg + (size_t)row * DIM + ch);
        }
        if (t < 16) cp16(sM + s * 256 + t * 16, mb + kt * 64 + t * 4);
        cp_commit();
    };

    issue_kv(0, 0); issue_kv(1, 1);

    // stage Q (pre-scaled by SCALE*log2e in the projection) into Ps
    {
        int row0 = t >> 3, ch = (t & 7) * 8;
#pragma unroll
        for (int r = 0; r < 4; r++) {
            int row = row0 + r * 32;
            *(uint4*)&Ps[row * HSR + ch] = *(const uint4*)(Qb + (size_t)row * DIM + ch);
        }
    }
    __syncthreads();

    unsigned qf[4][4];
    {
        unsigned qbase = sP + (unsigned)((16 * w + rA) * HSR + kA) * 2;
#pragma unroll
        for (int ks = 0; ks < 4; ks++)
            ldsm4(qf[ks][0], qf[ks][1], qf[ks][2], qf[ks][3], qbase + ks * 32);
    }

    float O[8][4];
#pragma unroll
    for (int nt = 0; nt < 8; nt++)
#pragma unroll
        for (int i = 0; i < 4; i++) O[nt][i] = 0.f;
    float Ol[4] = {0.f, 0.f, 0.f, 0.f};
    float mr0 = -1e30f, mr1 = -1e30f;
    unsigned Pp01[8], Pp23[8];    // P of the previous tile (A-fragments)

    const int NT = LK / 64;       // 32
    for (int kt = 0; kt < NT; kt++) {
        if (kt + 1 < NT) asm volatile("cp.async.wait_group 1;");
        else             asm volatile("cp.async.wait_group 0;");
        __syncthreads();
        if (kt + 2 < NT) issue_kv(kt + 2, (kt + 2) & 3);

        const int sb = kt & 3;
        const int pb = (kt - 1) & 3;
        const int* Mc = Msm + sb * 64;
        const unsigned kbase = sKV + (unsigned)(sb * KV_STAGE + rB * HSR + kB) * 2;
        const unsigned vbase = sKV + (unsigned)(pb * KV_STAGE + KV_TILE + rV * HSR + dV) * 2;

        // ---- S_kt MMAs (issued first; results needed only by softmax below) ----
        float S[8][4];
#pragma unroll
        for (int nt = 0; nt < 8; nt++)
#pragma unroll
            for (int i = 0; i < 4; i++) S[nt][i] = 0.f;

#pragma unroll
        for (int ks = 0; ks < 4; ks++) {
#pragma unroll
            for (int ntp = 0; ntp < 4; ntp++) {
                unsigned b0, b1, b2, b3;
                ldsm4(b0, b1, b2, b3, kbase + (unsigned)(ntp * 16 * HSR) * 2 + ks * 32);
                mma16(S[2 * ntp],     qf[ks], b0, b1);
                mma16(S[2 * ntp + 1], qf[ks], b2, b3);
            }
        }

        // ---- PV_{kt-1}: independent of S_kt; fills tensor pipe during softmax ----
        if (kt) {
#pragma unroll
            for (int kk = 0; kk < 4; kk++) {
                unsigned pa[4];
                pa[0] = Pp01[2 * kk];     pa[1] = Pp23[2 * kk];
                pa[2] = Pp01[2 * kk + 1]; pa[3] = Pp23[2 * kk + 1];
                mma16(Ol, pa, onesb, onesb);
#pragma unroll
                for (int ntp = 0; ntp < 4; ntp++) {
                    unsigned v0, v1, v2, v3;
                    ldsm4t(v0, v1, v2, v3,
                           vbase + (unsigned)(kk * 16 * HSR) * 2 + ntp * 32);
                    mma16(O[2 * ntp],     pa, v0, v1);
                    mma16(O[2 * ntp + 1], pa, v2, v3);
                }
            }
        }

        // ---- softmax on S_kt (runs while PV drains) ----
#pragma unroll
        for (int nt = 0; nt < 8; nt++) {
            if (!Mc[nt * 8 + 2 * c4])     { S[nt][0] = -1e30f; S[nt][2] = -1e30f; }
            if (!Mc[nt * 8 + 2 * c4 + 1]) { S[nt][1] = -1e30f; S[nt][3] = -1e30f; }
        }

        float mx0 = -1e30f, mx1 = -1e30f;
#pragma unroll
        for (int nt = 0; nt < 8; nt++) {
            mx0 = fmaxf(mx0, fmaxf(S[nt][0], S[nt][1]));
            mx1 = fmaxf(mx1, fmaxf(S[nt][2], S[nt][3]));
        }
        mx0 = fmaxf(mx0, __shfl_xor_sync(0xffffffffu, mx0, 1));
        mx0 = fmaxf(mx0, __shfl_xor_sync(0xffffffffu, mx0, 2));
        mx1 = fmaxf(mx1, __shfl_xor_sync(0xffffffffu, mx1, 1));
        mx1 = fmaxf(mx1, __shfl_xor_sync(0xffffffffu, mx1, 2));

        float mn0 = fmaxf(mr0, mx0), mn1 = fmaxf(mr1, mx1);
        float a0 = ex2(mr0 - mn0), a1 = ex2(mr1 - mn1);
        mr0 = mn0; mr1 = mn1;

        // rescale AFTER the PV add (O, l are at scale m_{kt-1} until here)
#pragma unroll
        for (int nt = 0; nt < 8; nt++) {
            O[nt][0] *= a0; O[nt][1] *= a0; O[nt][2] *= a1; O[nt][3] *= a1;
        }
        Ol[0] *= a0; Ol[1] *= a0; Ol[2] *= a1; Ol[3] *= a1;

        // P_kt in fp16 pairs (ready for next iteration's PV)
#pragma unroll
        for (int nt = 0; nt < 8; nt++) {
            Pp01[nt] = h2ex2(S[nt][0] - mn0, S[nt][1] - mn0);
            Pp23[nt] = h2ex2(S[nt][2] - mn1, S[nt][3] - mn1);
        }
    }

    // ---- final PV for tile NT-1 ----
    {
        const unsigned vbase = sKV +
            (unsigned)(((NT - 1) & 3) * KV_STAGE + KV_TILE + rV * HSR + dV) * 2;
#pragma unroll
        for (int kk = 0; kk < 4; kk++) {
            unsigned pa[4];
            pa[0] = Pp01[2 * kk];     pa[1] = Pp23[2 * kk];
            pa[2] = Pp01[2 * kk + 1]; pa[3] = Pp23[2 * kk + 1];
            mma16(Ol, pa, onesb, onesb);
#pragma unroll
            for (int ntp = 0; ntp < 4; ntp++) {
                unsigned v0, v1, v2, v3;
                ldsm4t(v0, v1, v2, v3,
                       vbase + (unsigned)(kk * 16 * HSR) * 2 + ntp * 32);
                mma16(O[2 * ntp],     pa, v0, v1);
                mma16(O[2 * ntp + 1], pa, v2, v3);
            }
        }
    }

    // l lives in column 0 (lane c4==0): broadcast within each quad
    float l0 = __shfl_sync(0xffffffffu, Ol[0], lane & 28);
    float l1 = __shfl_sync(0xffffffffu, Ol[2], lane & 28);
    float inv0 = 1.f / l0, inv1 = 1.f / l1;

    __half* Ob = Ao + ((size_t)(b * LQ + qt * 128)) * DIM + h * HD;
    int row0 = 16 * w + g;
#pragma unroll
    for (int nt = 0; nt < 8; nt++) {
        int col = nt * 8 + 2 * c4;
        *(__half2*)&Ob[(size_t)row0 * DIM + col] =
            __floats2half2_rn(O[nt][0] * inv0, O[nt][1] * inv0);
        *(__half2*)&Ob[(size_t)(row0 + 8) * DIM + col] =
            __floats2half2_rn(O[nt][2] * inv1, O[nt][3] * inv1);
    }
}

// ---------------- launch ----------------
extern "C" void kernel_launch(void* const* d_in, const int* in_sizes, int n_in,
                              void* d_out, int out_size)
{
    const float* q       = (const float*)d_in[0];
    const float* k       = (const float*)d_in[1];
    const float* v       = (const float*)d_in[2];
    const int*   kv_mask = (const int*)d_in[3];
    const float* Wq      = (const float*)d_in[4];
    const float* bq      = (const float*)d_in[5];
    const float* Wk      = (const float*)d_in[6];
    const float* bk      = (const float*)d_in[7];
    const float* Wv      = (const float*)d_in[8];
    const float* bv      = (const float*)d_in[9];
    const float* Wo      = (const float*)d_in[10];
    const float* bo      = (const float*)d_in[11];
    float* out = (float*)d_out;

    __half *qh, *kh, *vh, *wq, *wk, *wv, *wo, *Qp, *Kp, *Vp, *Ao;
    cudaGetSymbolAddress((void**)&qh, g_qh);
    cudaGetSymbolAddress((void**)&kh, g_kh);
    cudaGetSymbolAddress((void**)&vh, g_vh);
    cudaGetSymbolAddress((void**)&wq, g_wq);
    cudaGetSymbolAddress((void**)&wk, g_wk);
    cudaGetSymbolAddress((void**)&wv, g_wv);
    cudaGetSymbolAddress((void**)&wo, g_wo);
    cudaGetSymbolAddress((void**)&Qp, g_Qp);
    cudaGetSymbolAddress((void**)&Kp, g_Kp);
    cudaGetSymbolAddress((void**)&Vp, g_Vp);
    cudaGetSymbolAddress((void**)&Ao, g_Ao);

    cudaFuncSetAttribute(gemm_h<true>,  cudaFuncAttributeMaxDynamicSharedMemorySize, GEMM_SMEM);
    cudaFuncSetAttribute(gemm_h<false>, cudaFuncAttributeMaxDynamicSharedMemorySize, GEMM_SMEM);
    cudaFuncSetAttribute(attn_h, cudaFuncAttributeMaxDynamicSharedMemorySize, ATT_SMEM);

    const int ACT4 = BATCH * LQ * DIM / 4;
    const int W4   = DIM * DIM / 4;
    conv3<<<dim3(ACT4 / 256, 3), 256>>>(q, k, v, qh, kh, vh, ACT4);
    conv4<<<dim3(W4 / 256, 4), 256>>>(Wq, Wk, Wv, Wo, wq, wk, wv, wo, W4);

    gemm_h<true><<<dim3(DIM / GBN, (BATCH * LQ) / GBM, 3), 256, GEMM_SMEM>>>(
        qh, kh, vh, wq, wk, wv, bq, bk, bv, Qp, Kp, Vp,
        QSCALE, 1.0f, 1.0f);

    attn_h<<<dim3(LQ / 128, NH, BATCH), 256, ATT_SMEM>>>(Qp, Kp, Vp, kv_mask, Ao);

    gemm_h<false><<<dim3(DIM / GBN, (BATCH * LQ) / GBM, 1), 256, GEMM_SMEM>>>(
        Ao, Ao, Ao, wo, wo, wo, bo, bo, bo, out, out, out,
        1.0f, 1.0f, 1.0f);
}

// round 17
// speedup vs baseline: 1.0521x; 1.0396x over previous
#include <cuda_runtime.h>
#include <cuda_fp16.h>

#define DIM 1024
#define NH 16
#define HD 64
#define BATCH 2
#define LQ 2048
#define LK 2048
// SCALE * log2(e): folded into the Q projection epilogue (fp32, pre-rounding)
#define QSCALE 0.18033688011112042f

// ---------------- scratch (allocation-free: __device__ globals) ----------------
__device__ __half g_qh[BATCH * LQ * DIM];
__device__ __half g_kh[BATCH * LK * DIM];
__device__ __half g_vh[BATCH * LK * DIM];
__device__ __half g_wq[DIM * DIM];
__device__ __half g_wk[DIM * DIM];
__device__ __half g_wv[DIM * DIM];
__device__ __half g_wo[DIM * DIM];
__device__ __half g_Qp[BATCH * LQ * DIM];
__device__ __half g_Kp[BATCH * LK * DIM];
__device__ __half g_Vp[BATCH * LK * DIM];
__device__ __half g_Ao[BATCH * LQ * DIM];

// ---------------- helpers ----------------
__device__ __forceinline__ float ex2(float x) {
    float y;
    asm("ex2.approx.ftz.f32 %0, %1;" : "=f"(y) : "f"(x));
    return y;
}
__device__ __forceinline__ void mma16(float* c, const unsigned* a, unsigned b0, unsigned b1) {
    asm volatile(
        "mma.sync.aligned.m16n8k16.row.col.f32.f16.f16.f32 "
        "{%0,%1,%2,%3}, {%4,%5,%6,%7}, {%8,%9}, {%0,%1,%2,%3};"
        : "+f"(c[0]), "+f"(c[1]), "+f"(c[2]), "+f"(c[3])
        : "r"(a[0]), "r"(a[1]), "r"(a[2]), "r"(a[3]), "r"(b0), "r"(b1));
}
__device__ __forceinline__ void ldsm4(unsigned& r0, unsigned& r1, unsigned& r2,
                                      unsigned& r3, unsigned addr) {
    asm volatile("ldmatrix.sync.aligned.m8n8.x4.shared.b16 {%0,%1,%2,%3}, [%4];"
                 : "=r"(r0), "=r"(r1), "=r"(r2), "=r"(r3) : "r"(addr));
}
__device__ __forceinline__ void ldsm4t(unsigned& r0, unsigned& r1, unsigned& r2,
                                       unsigned& r3, unsigned addr) {
    asm volatile("ldmatrix.sync.aligned.m8n8.x4.trans.shared.b16 {%0,%1,%2,%3}, [%4];"
                 : "=r"(r0), "=r"(r1), "=r"(r2), "=r"(r3) : "r"(addr));
}
__device__ __forceinline__ void cp16(unsigned s, const void* g) {
    asm volatile("cp.async.cg.shared.global [%0], [%1], 16;" :: "r"(s), "l"(g));
}
__device__ __forceinline__ void cp_commit() { asm volatile("cp.async.commit_group;"); }

// ---------------- convert kernels: f32 -> fp16 (RNE) ----------------
__global__ __launch_bounds__(256) void conv3(
    const float* __restrict__ a, const float* __restrict__ b, const float* __restrict__ c,
    __half* __restrict__ oa, __half* __restrict__ ob, __half* __restrict__ oc, int n4)
{
    const float* x = blockIdx.y == 0 ? a : blockIdx.y == 1 ? b : c;
    __half*      y = blockIdx.y == 0 ? oa : blockIdx.y == 1 ? ob : oc;
    int i = blockIdx.x * blockDim.x + threadIdx.x;
    if (i < n4) {
        float4 v = ((const float4*)x)[i];
        ((__half2*)y)[2 * i]     = __floats2half2_rn(v.x, v.y);
        ((__half2*)y)[2 * i + 1] = __floats2half2_rn(v.z, v.w);
    }
}
__global__ __launch_bounds__(256) void conv4(
    const float* __restrict__ a, const float* __restrict__ b,
    const float* __restrict__ c, const float* __restrict__ d,
    __half* __restrict__ oa, __half* __restrict__ ob,
    __half* __restrict__ oc, __half* __restrict__ od, int n4)
{
    const float* x = blockIdx.y == 0 ? a : blockIdx.y == 1 ? b : blockIdx.y == 2 ? c : d;
    __half*      y = blockIdx.y == 0 ? oa : blockIdx.y == 1 ? ob : blockIdx.y == 2 ? oc : od;
    int i = blockIdx.x * blockDim.x + threadIdx.x;
    if (i < n4) {
        float4 v = ((const float4*)x)[i];
        ((__half2*)y)[2 * i]     = __floats2half2_rn(v.x, v.y);
        ((__half2*)y)[2 * i + 1] = __floats2half2_rn(v.z, v.w);
    }
}

// ===== GEMM: C = (A @ W^T + bias) * osc, fp16 HMMA, 2-stage (2 CTAs/SM) =====
#define GBM 128
#define GBN 128
#define GBK 64
#define HSR 72
#define GBUF (2 * GBM * HSR)
#define GEMM_SMEM (2 * GBUF * 2)

template <bool HALF_OUT>
__global__ __launch_bounds__(256) void gemm_h(
    const __half* __restrict__ A0, const __half* __restrict__ A1,
    const __half* __restrict__ A2,
    const __half* __restrict__ W0, const __half* __restrict__ W1,
    const __half* __restrict__ W2,
    const float* __restrict__ B0, const float* __restrict__ B1,
    const float* __restrict__ B2,
    void* __restrict__ C0, void* __restrict__ C1, void* __restrict__ C2,
    float s0_, float s1_, float s2_)
{
    extern __shared__ __half smh[];
    const unsigned sS = (unsigned)__cvta_generic_to_shared(smh);

    const int z = blockIdx.z;
    const __half* A  = z == 0 ? A0 : z == 1 ? A1 : A2;
    const __half* W  = z == 0 ? W0 : z == 1 ? W1 : W2;
    const float* bias = z == 0 ? B0 : z == 1 ? B1 : B2;
    void* Cv = z == 0 ? C0 : z == 1 ? C1 : C2;
    const float osc = z == 0 ? s0_ : z == 1 ? s1_ : s2_;

    const int t = threadIdx.x, lane = t & 31, wid = t >> 5;
    const int wm = (wid >> 2) * 64;
    const int wn = (wid & 3) * 32;
    const int c4 = lane & 3, g = lane >> 2, lrow = lane & 7;
    const int rA = ((lane >> 3) & 1) * 8 + lrow;  const int kA = (lane >> 4) * 8;
    const int rB = ((lane >> 4) & 1) * 8 + lrow;  const int kB = ((lane >> 3) & 1) * 8;
    const int bm = blockIdx.y * GBM, bn = blockIdx.x * GBN;

    const int srow = t >> 3;
    const int scol = (t & 7) * 8;

    float acc[4][4][4];
#pragma unroll
    for (int mt = 0; mt < 4; mt++)
#pragma unroll
        for (int nt = 0; nt < 4; nt++)
#pragma unroll
            for (int i = 0; i < 4; i++) acc[mt][nt][i] = 0.f;

    auto issue = [&](int kt, int b) {
        int k0 = kt * GBK;
        unsigned sbuf = sS + (unsigned)(b * GBUF) * 2;
#pragma unroll
        for (int r = 0; r < 4; r++) {
            int row = srow + r * 32;
            cp16(sbuf + (unsigned)(row * HSR + scol) * 2,
                 A + (size_t)(bm + row) * DIM + k0 + scol);
            cp16(sbuf + (unsigned)(GBM * HSR + row * HSR + scol) * 2,
                 W + (size_t)(bn + row) * DIM + k0 + scol);
        }
        cp_commit();
    };

    const int NT = DIM / GBK;   // 16
    issue(0, 0);

    for (int kt = 0; kt < NT; kt++) {
        const int b = kt & 1;
        asm volatile("cp.async.wait_group 0;");
        __syncthreads();
        if (kt + 1 < NT) issue(kt + 1, (kt + 1) & 1);

        const unsigned abase = sS + (unsigned)(b * GBUF + (wm + rA) * HSR + kA) * 2;
        const unsigned bbase = sS + (unsigned)(b * GBUF + GBM * HSR + (wn + rB) * HSR + kB) * 2;

#pragma unroll
        for (int ks = 0; ks < 4; ks++) {
            unsigned af[4][4], bf[2][4];
#pragma unroll
            for (int mt = 0; mt < 4; mt++)
                ldsm4(af[mt][0], af[mt][1], af[mt][2], af[mt][3],
                      abase + (unsigned)(mt * 16 * HSR) * 2 + ks * 32);
#pragma unroll
            for (int ntp = 0; ntp < 2; ntp++)
                ldsm4(bf[ntp][0], bf[ntp][1], bf[ntp][2], bf[ntp][3],
                      bbase + (unsigned)(ntp * 16 * HSR) * 2 + ks * 32);
#pragma unroll
            for (int mt = 0; mt < 4; mt++)
#pragma unroll
                for (int ntp = 0; ntp < 2; ntp++) {
                    mma16(acc[mt][2 * ntp],     af[mt], bf[ntp][0], bf[ntp][1]);
                    mma16(acc[mt][2 * ntp + 1], af[mt], bf[ntp][2], bf[ntp][3]);
                }
        }
    }

#pragma unroll
    for (int mt = 0; mt < 4; mt++) {
        int row = bm + wm + mt * 16 + g;
#pragma unroll
        for (int nt = 0; nt < 4; nt++) {
            int col = bn + wn + nt * 8 + 2 * c4;
            float b0 = __ldg(&bias[col]);
            float b1 = __ldg(&bias[col + 1]);
            float v00 = (acc[mt][nt][0] + b0) * osc, v01 = (acc[mt][nt][1] + b1) * osc;
            float v10 = (acc[mt][nt][2] + b0) * osc, v11 = (acc[mt][nt][3] + b1) * osc;
            if (HALF_OUT) {
                __half* C = (__half*)Cv;
                *(__half2*)&C[(size_t)row * DIM + col]       = __floats2half2_rn(v00, v01);
                *(__half2*)&C[(size_t)(row + 8) * DIM + col] = __floats2half2_rn(v10, v11);
            } else {
                float* C = (float*)Cv;
                *(float2*)&C[(size_t)row * DIM + col]       = make_float2(v00, v01);
                *(float2*)&C[(size_t)(row + 8) * DIM + col] = make_float2(v10, v11);
            }
        }
    }
}

// ========== flash attention: PV pipelined; shfl row-sums in the PV shadow ==========
#define KV_TILE  (64 * HSR)
#define KV_STAGE (2 * KV_TILE)
#define PS_OFF   (4 * KV_STAGE)
#define MSK_OFF  ((PS_OFF + 128 * HSR) * 2)
#define ATT_SMEM (MSK_OFF + 4 * 64 * 4)

__global__ __launch_bounds__(256, 2) void attn_h(
    const __half* __restrict__ Qp, const __half* __restrict__ Kp,
    const __half* __restrict__ Vp, const int* __restrict__ kv_mask,
    __half* __restrict__ Ao)
{
    extern __shared__ __half smh[];
    __half* Ps = smh + PS_OFF;
    int*   Msm = (int*)((char*)smh + MSK_OFF);

    const unsigned sKV = (unsigned)__cvta_generic_to_shared(smh);
    const unsigned sP  = (unsigned)__cvta_generic_to_shared(Ps);
    const unsigned sM  = (unsigned)__cvta_generic_to_shared(Msm);

    const int t = threadIdx.x, lane = t & 31, w = t >> 5;
    const int c4 = lane & 3, g = lane >> 2, lrow = lane & 7;
    const int rA = lane & 15;                     const int kA = (lane >> 4) * 8;
    const int rB = ((lane >> 4) & 1) * 8 + lrow;  const int kB = ((lane >> 3) & 1) * 8;
    const int rV = ((lane >> 3) & 1) * 8 + lrow;  const int dV = (lane >> 4) * 8;
    const int qt = blockIdx.x, h = blockIdx.y, b = blockIdx.z;

    const __half* Qb = Qp + ((size_t)(b * LQ + qt * 128)) * DIM + h * HD;
    const __half* Kb = Kp + (size_t)b * LK * DIM + h * HD;
    const __half* Vb = Vp + (size_t)b * LK * DIM + h * HD;
    const int*    mb = kv_mask + b * LK;

    auto issue_kv = [&](int kt, int s) {
        const __half* Kg = Kb + (size_t)(kt * 64) * DIM;
        const __half* Vg = Vb + (size_t)(kt * 64) * DIM;
        int row0 = t >> 3, ch = (t & 7) * 8;
        unsigned base = sKV + (unsigned)(s * KV_STAGE) * 2;
#pragma unroll
        for (int r = 0; r < 2; r++) {
            int row = row0 + r * 32;
            cp16(base + (unsigned)(row * HSR + ch) * 2,
                 Kg + (size_t)row * DIM + ch);
            cp16(base + (unsigned)(KV_TILE + row * HSR + ch) * 2,
                 Vg + (size_t)row * DIM + ch);
        }
        if (t < 16) cp16(sM + s * 256 + t * 16, mb + kt * 64 + t * 4);
        cp_commit();
    };

    issue_kv(0, 0); issue_kv(1, 1);

    // stage Q (pre-scaled by SCALE*log2e in the projection) into Ps
    {
        int row0 = t >> 3, ch = (t & 7) * 8;
#pragma unroll
        for (int r = 0; r < 4; r++) {
            int row = row0 + r * 32;
            *(uint4*)&Ps[row * HSR + ch] = *(const uint4*)(Qb + (size_t)row * DIM + ch);
        }
    }
    __syncthreads();

    unsigned qf[4][4];
    {
        unsigned qbase = sP + (unsigned)((16 * w + rA) * HSR + kA) * 2;
#pragma unroll
        for (int ks = 0; ks < 4; ks++)
            ldsm4(qf[ks][0], qf[ks][1], qf[ks][2], qf[ks][3], qbase + ks * 32);
    }

    float O[8][4];
#pragma unroll
    for (int nt = 0; nt < 8; nt++)
#pragma unroll
        for (int i = 0; i < 4; i++) O[nt][i] = 0.f;
    float mr0 = -1e30f, mr1 = -1e30f, lr0 = 0.f, lr1 = 0.f;
    unsigned Pp01[8], Pp23[8];    // P of the previous tile (A-fragments)

    const int NT = LK / 64;       // 32
    for (int kt = 0; kt < NT; kt++) {
        if (kt + 1 < NT) asm volatile("cp.async.wait_group 1;");
        else             asm volatile("cp.async.wait_group 0;");
        __syncthreads();
        if (kt + 2 < NT) issue_kv(kt + 2, (kt + 2) & 3);

        const int sb = kt & 3;
        const int pb = (kt - 1) & 3;
        const int* Mc = Msm + sb * 64;
        const unsigned kbase = sKV + (unsigned)(sb * KV_STAGE + rB * HSR + kB) * 2;
        const unsigned vbase = sKV + (unsigned)(pb * KV_STAGE + KV_TILE + rV * HSR + dV) * 2;

        // ---- S_kt MMAs ----
        float S[8][4];
#pragma unroll
        for (int nt = 0; nt < 8; nt++)
#pragma unroll
            for (int i = 0; i < 4; i++) S[nt][i] = 0.f;

#pragma unroll
        for (int ks = 0; ks < 4; ks++) {
#pragma unroll
            for (int ntp = 0; ntp < 4; ntp++) {
                unsigned b0, b1, b2, b3;
                ldsm4(b0, b1, b2, b3, kbase + (unsigned)(ntp * 16 * HSR) * 2 + ks * 32);
                mma16(S[2 * ntp],     qf[ks], b0, b1);
                mma16(S[2 * ntp + 1], qf[ks], b2, b3);
            }
        }

        // ---- PV_{kt-1}: independent; fills tensor pipe during softmax ----
        if (kt) {
#pragma unroll
            for (int kk = 0; kk < 4; kk++) {
                unsigned pa[4];
                pa[0] = Pp01[2 * kk];     pa[1] = Pp23[2 * kk];
                pa[2] = Pp01[2 * kk + 1]; pa[3] = Pp23[2 * kk + 1];
#pragma unroll
                for (int ntp = 0; ntp < 4; ntp++) {
                    unsigned v0, v1, v2, v3;
                    ldsm4t(v0, v1, v2, v3,
                           vbase + (unsigned)(kk * 16 * HSR) * 2 + ntp * 32);
                    mma16(O[2 * ntp],     pa, v0, v1);
                    mma16(O[2 * ntp + 1], pa, v2, v3);
                }
            }
        }

        // ---- softmax on S_kt (scalar pipes; runs under the PV drain) ----
#pragma unroll
        for (int nt = 0; nt < 8; nt++) {
            if (!Mc[nt * 8 + 2 * c4])     { S[nt][0] = -1e30f; S[nt][2] = -1e30f; }
            if (!Mc[nt * 8 + 2 * c4 + 1]) { S[nt][1] = -1e30f; S[nt][3] = -1e30f; }
        }

        float mx0 = -1e30f, mx1 = -1e30f;
#pragma unroll
        for (int nt = 0; nt < 8; nt++) {
            mx0 = fmaxf(mx0, fmaxf(S[nt][0], S[nt][1]));
            mx1 = fmaxf(mx1, fmaxf(S[nt][2], S[nt][3]));
        }
        mx0 = fmaxf(mx0, __shfl_xor_sync(0xffffffffu, mx0, 1));
        mx0 = fmaxf(mx0, __shfl_xor_sync(0xffffffffu, mx0, 2));
        mx1 = fmaxf(mx1, __shfl_xor_sync(0xffffffffu, mx1, 1));
        mx1 = fmaxf(mx1, __shfl_xor_sync(0xffffffffu, mx1, 2));

        float mn0 = fmaxf(mr0, mx0), mn1 = fmaxf(mr1, mx1);
        float a0 = ex2(mr0 - mn0), a1 = ex2(mr1 - mn1);
        mr0 = mn0; mr1 = mn1;

        // rescale O AFTER the PV add (O was at scale m_{kt-1}, like P_{kt-1})
#pragma unroll
        for (int nt = 0; nt < 8; nt++) {
            O[nt][0] *= a0; O[nt][1] *= a0; O[nt][2] *= a1; O[nt][3] *= a1;
        }

        // P_kt (f32 exp -> fp16 A-frags) + row sums in the PV shadow
        float s0 = 0.f, s1 = 0.f;
#pragma unroll
        for (int nt = 0; nt < 8; nt++) {
            float p0 = ex2(S[nt][0] - mn0);
            float p1 = ex2(S[nt][1] - mn0);
            float p2 = ex2(S[nt][2] - mn1);
            float p3 = ex2(S[nt][3] - mn1);
            s0 += p0 + p1; s1 += p2 + p3;
            __half2 h01 = __floats2half2_rn(p0, p1);
            __half2 h23 = __floats2half2_rn(p2, p3);
            Pp01[nt] = *(unsigned*)&h01;
            Pp23[nt] = *(unsigned*)&h23;
        }
        s0 += __shfl_xor_sync(0xffffffffu, s0, 1);
        s0 += __shfl_xor_sync(0xffffffffu, s0, 2);
        s1 += __shfl_xor_sync(0xffffffffu, s1, 1);
        s1 += __shfl_xor_sync(0xffffffffu, s1, 2);
        lr0 = lr0 * a0 + s0;
        lr1 = lr1 * a1 + s1;
    }

    // ---- final PV for tile NT-1 ----
    {
        const unsigned vbase = sKV +
            (unsigned)(((NT - 1) & 3) * KV_STAGE + KV_TILE + rV * HSR + dV) * 2;
#pragma unroll
        for (int kk = 0; kk < 4; kk++) {
            unsigned pa[4];
            pa[0] = Pp01[2 * kk];     pa[1] = Pp23[2 * kk];
            pa[2] = Pp01[2 * kk + 1]; pa[3] = Pp23[2 * kk + 1];
#pragma unroll
            for (int ntp = 0; ntp < 4; ntp++) {
                unsigned v0, v1, v2, v3;
                ldsm4t(v0, v1, v2, v3,
                       vbase + (unsigned)(kk * 16 * HSR) * 2 + ntp * 32);
                mma16(O[2 * ntp],     pa, v0, v1);
                mma16(O[2 * ntp + 1], pa, v2, v3);
            }
        }
    }

    float inv0 = 1.f / lr0, inv1 = 1.f / lr1;
    __half* Ob = Ao + ((size_t)(b * LQ + qt * 128)) * DIM + h * HD;
    int row0 = 16 * w + g;
#pragma unroll
    for (int nt = 0; nt < 8; nt++) {
        int col = nt * 8 + 2 * c4;
        *(__half2*)&Ob[(size_t)row0 * DIM + col] =
            __floats2half2_rn(O[nt][0] * inv0, O[nt][1] * inv0);
        *(__half2*)&Ob[(size_t)(row0 + 8) * DIM + col] =
            __floats2half2_rn(O[nt][2] * inv1, O[nt][3] * inv1);
    }
}

// ---------------- launch ----------------
extern "C" void kernel_launch(void* const* d_in, const int* in_sizes, int n_in,
                              void* d_out, int out_size)
{
    const float* q       = (const float*)d_in[0];
    const float* k       = (const float*)d_in[1];
    const float* v       = (const float*)d_in[2];
    const int*   kv_mask = (const int*)d_in[3];
    const float* Wq      = (const float*)d_in[4];
    const float* bq      = (const float*)d_in[5];
    const float* Wk      = (const float*)d_in[6];
    const float* bk      = (const float*)d_in[7];
    const float* Wv      = (const float*)d_in[8];
    const float* bv      = (const float*)d_in[9];
    const float* Wo      = (const float*)d_in[10];
    const float* bo      = (const float*)d_in[11];
    float* out = (float*)d_out;

    __half *qh, *kh, *vh, *wq, *wk, *wv, *wo, *Qp, *Kp, *Vp, *Ao;
    cudaGetSymbolAddress((void**)&qh, g_qh);
    cudaGetSymbolAddress((void**)&kh, g_kh);
    cudaGetSymbolAddress((void**)&vh, g_vh);
    cudaGetSymbolAddress((void**)&wq, g_wq);
    cudaGetSymbolAddress((void**)&wk, g_wk);
    cudaGetSymbolAddress((void**)&wv, g_wv);
    cudaGetSymbolAddress((void**)&wo, g_wo);
    cudaGetSymbolAddress((void**)&Qp, g_Qp);
    cudaGetSymbolAddress((void**)&Kp, g_Kp);
    cudaGetSymbolAddress((void**)&Vp, g_Vp);
    cudaGetSymbolAddress((void**)&Ao, g_Ao);

    cudaFuncSetAttribute(gemm_h<true>,  cudaFuncAttributeMaxDynamicSharedMemorySize, GEMM_SMEM);
    cudaFuncSetAttribute(gemm_h<false>, cudaFuncAttributeMaxDynamicSharedMemorySize, GEMM_SMEM);
    cudaFuncSetAttribute(attn_h, cudaFuncAttributeMaxDynamicSharedMemorySize, ATT_SMEM);

    const int ACT4 = BATCH * LQ * DIM / 4;
    const int W4   = DIM * DIM / 4;
    conv3<<<dim3(ACT4 / 256, 3), 256>>>(q, k, v, qh, kh, vh, ACT4);
    conv4<<<dim3(W4 / 256, 4), 256>>>(Wq, Wk, Wv, Wo, wq, wk, wv, wo, W4);

    gemm_h<true><<<dim3(DIM / GBN, (BATCH * LQ) / GBM, 3), 256, GEMM_SMEM>>>(
        qh, kh, vh, wq, wk, wv, bq, bk, bv, Qp, Kp, Vp,
        QSCALE, 1.0f, 1.0f);

    attn_h<<<dim3(LQ / 128, NH, BATCH), 256, ATT_SMEM>>>(Qp, Kp, Vp, kv_mask, Ao);

    gemm_h<false><<<dim3(DIM / GBN, (BATCH * LQ) / GBM, 1), 256, GEMM_SMEM>>>(
        Ao, Ao, Ao, wo, wo, wo, bo, bo, bo, out, out, out,
        1.0f, 1.0f, 1.0f);
}